// round 14
// baseline (speedup 1.0000x reference)
#include <cuda_runtime.h>

// ---------------------------------------------------------------------------
// MeanPooling: out[b,:] = mean of x[i,:] over rows i with batch[i]==b
// x: (N,128) fp32, batch: (N,) sorted int64-or-int32, out: (4096,128) fp32
// R10: SINGLE kernel, segment-per-warp ownership. Warp w finds its segment's
// row range [lo,hi) via warp-cooperative 32-ary lower_bound (5 rounds for
// n=1M), streams those rows branch-free, scales by 1/(hi-lo), plain-stores
// the 128 output floats. No atomics, no zeroing, no scratch, no epilogue.
// Every output float written exactly once -> deterministic each replay.
// ---------------------------------------------------------------------------

#define D 128
#define FULL 0xFFFFFFFFu

// Warp-cooperative lower_bound: first index i in [0,n] with b[i] >= key.
// Invariant: b[lo] < key (lo==-1 virtual -inf), b[hi] >= key (hi==n virtual
// +inf). Each round 32 lanes probe evenly spaced interior pivots; monotone
// predicate -> ballot popcount gives the bracket. ~log32(n) rounds.
__device__ __forceinline__ int wlower_bound(const int* __restrict__ bw,
                                            int ish, int n, int key,
                                            int lane) {
    int lo = -1, hi = n;
    while (hi - lo > 1) {
        int span = hi - lo - 1;   // # interior candidates
        int t = lo + 1 + (int)(((long long)span * lane) >> 5);
        int v = bw[t << ish];
        unsigned m = __ballot_sync(FULL, v < key);   // monotone prefix
        int k = __popc(m);
        int nlo = (k > 0) ? lo + 1 + (int)(((long long)span * (k - 1)) >> 5)
                          : lo;
        int nhi = (k < 32) ? lo + 1 + (int)(((long long)span * k) >> 5)
                           : hi;
        lo = nlo;
        hi = nhi;
    }
    return hi;
}

__global__ void __launch_bounds__(128, 8)
k_mean(const float4* __restrict__ x4, const void* __restrict__ batch,
       float4* __restrict__ out4, int n, int B) {
    const int lane = threadIdx.x & 31;
    const int w = blockIdx.x * (blockDim.x >> 5) + (threadIdx.x >> 5);
    if (w >= B) return;

    // ---- dtype detect (warp-parallel, one ballot round) ----
    // int64 LE: odd 32-bit words are high halves == 0 (values < 4096).
    // int32 sorted data: words near the end ~ num_graphs-1 (nonzero).
    const unsigned int* bu = (const unsigned int*)batch;
    int top = n - 1;
    if ((top & 1) == 0) top--;                  // largest odd word index
    int di = top - 2 * lane;
    unsigned int dv = (di >= 1) ? bu[di] : 0u;
    unsigned int nzm = __ballot_sync(FULL, dv != 0u);
    const int ish = (nzm == 0u) ? 1 : 0;        // int64: low word at bw[2i]
    const int* bw = (const int*)batch;

    // ---- segment bounds via two warp-cooperative searches ----
    int lo = wlower_bound(bw, ish, n, w, lane);
    int hi = wlower_bound(bw, ish, n, w + 1, lane);

    // ---- branch-free streaming sum over [lo, hi) ----
    float4 acc = make_float4(0.f, 0.f, 0.f, 0.f);
    int r = lo;
    for (; r + 4 <= hi; r += 4) {
        const float4* p = x4 + (size_t)r * 32 + lane;
        float4 v0 = __ldcs(p);
        float4 v1 = __ldcs(p + 32);
        float4 v2 = __ldcs(p + 64);
        float4 v3 = __ldcs(p + 96);
        acc.x += v0.x + v1.x + v2.x + v3.x;
        acc.y += v0.y + v1.y + v2.y + v3.y;
        acc.z += v0.z + v1.z + v2.z + v3.z;
        acc.w += v0.w + v1.w + v2.w + v3.w;
    }
    for (; r < hi; r++) {
        float4 v = __ldcs(x4 + (size_t)r * 32 + lane);
        acc.x += v.x; acc.y += v.y; acc.z += v.z; acc.w += v.w;
    }

    // ---- scale and store (empty segment -> rinv = 0 -> zeros) ----
    float rinv = (hi > lo) ? __frcp_rn((float)(hi - lo)) : 0.f;
    acc.x *= rinv; acc.y *= rinv; acc.z *= rinv; acc.w *= rinv;
    out4[(size_t)w * 32 + lane] = acc;
}

extern "C" void kernel_launch(void* const* d_in, const int* in_sizes, int n_in,
                              void* d_out, int out_size) {
    const float* x = (const float*)d_in[0];
    const void* batch = d_in[1];

    int n = in_sizes[0] / D;        // number of rows
    int B = out_size / D;           // number of segments (4096)

    int warps_per_block = 128 / 32; // 4
    int blocks = (B + warps_per_block - 1) / warps_per_block;
    k_mean<<<blocks, 128>>>((const float4*)x, batch, (float4*)d_out, n, B);
}